// round 3
// baseline (speedup 1.0000x reference)
#include <cuda_runtime.h>
#include <cstdint>

// Problem constants
#define BATCH 32
#define SEQ   128
#define DIM   256
#define MROWS (BATCH*SEQ)     // 4096
#define NSPLIT 16             // j-splits for pairwise kernel
#define JT    (SEQ/NSPLIT)    // 8 j-values per split
#define IT    16              // i-tile staged through smem

typedef unsigned long long ull;

// ---------------- scratch (device globals; no allocation allowed) -----------
__device__ float g_XL[MROWS * DIM];                 // Xl = Xe @ W_l^T + b_l
__device__ float g_XR[MROWS * DIM];                 // Xr = Xe @ W_r^T + b_r
__device__ float g_part[NSPLIT * BATCH * DIM];      // partial abs-sums
__device__ float g_lin[BATCH * DIM];                // 128*(colsum_l + colsum_r)

// ---------------- packed f32x2 helpers (sm_100+) ----------------------------
__device__ __forceinline__ ull fpk_dup(float x) {
    unsigned u = __float_as_uint(x);
    ull r;
    asm("mov.b64 %0, {%1, %1};" : "=l"(r) : "r"(u));
    return r;
}
__device__ __forceinline__ ull add2(ull a, ull b) {
    ull d;
    asm("add.rn.f32x2 %0, %1, %2;" : "=l"(d) : "l"(a), "l"(b));
    return d;
}
__device__ __forceinline__ ull fma2(ull a, ull b, ull c) {
    ull d;
    asm("fma.rn.f32x2 %0, %1, %2, %3;" : "=l"(d) : "l"(a), "l"(b), "l"(c));
    return d;
}
__device__ __forceinline__ float2 unpk(ull v) {
    unsigned lo, hi;
    asm("mov.b64 {%0, %1}, %2;" : "=r"(lo), "=r"(hi) : "l"(v));
    return make_float2(__uint_as_float(lo), __uint_as_float(hi));
}

// ---------------------------------------------------------------------------
// Kernel 1: fused embedding gather + dual GEMM
//   C[m, n] = sum_k emb[tok[m], k] * W[n, k] + bias[n]
//   grid.x = 64 (m-tiles of 64), grid.y = 8 (n-tiles of 64; 0-3 -> W_l, 4-7 -> W_r)
// ---------------------------------------------------------------------------
#define BM 64
#define BN 64
#define BK 32

__global__ void __launch_bounds__(256)
k_gemm(const int* __restrict__ X, const float* __restrict__ emb,
       const float* __restrict__ Wl, const float* __restrict__ bl,
       const float* __restrict__ Wr, const float* __restrict__ br)
{
    __shared__ float As[BK][BM + 4];   // row stride 68 floats = 272B (16B aligned)
    __shared__ float Bs[BK][BN + 4];
    __shared__ int   toks[BM];

    const int tid = threadIdx.x;
    const int bx = blockIdx.x, by = blockIdx.y;
    const bool isr = (by >= 4);
    const float* W    = isr ? Wr : Wl;
    const float* bias = isr ? br : bl;
    float*       Cout = isr ? g_XR : g_XL;
    const int nloc0 = (by & 3) * BN;

    if (tid < BM) toks[tid] = X[bx * BM + tid];
    __syncthreads();

    const int r  = tid >> 2;           // 0..63
    const int c0 = (tid & 3) * 8;      // 0,8,16,24
    const int ty = tid >> 4;           // 0..15
    const int tx = tid & 15;           // 0..15

    const float* arow = emb + (size_t)toks[r] * DIM;
    const float* brow = W   + (size_t)(nloc0 + r) * DIM;

    ull c2[4][2];
    #pragma unroll
    for (int i = 0; i < 4; i++) { c2[i][0] = 0ull; c2[i][1] = 0ull; }

    for (int k0 = 0; k0 < DIM; k0 += BK) {
        float4 a0 = *(const float4*)(arow + k0 + c0);
        float4 a1 = *(const float4*)(arow + k0 + c0 + 4);
        float4 b0 = *(const float4*)(brow + k0 + c0);
        float4 b1 = *(const float4*)(brow + k0 + c0 + 4);
        As[c0+0][r]=a0.x; As[c0+1][r]=a0.y; As[c0+2][r]=a0.z; As[c0+3][r]=a0.w;
        As[c0+4][r]=a1.x; As[c0+5][r]=a1.y; As[c0+6][r]=a1.z; As[c0+7][r]=a1.w;
        Bs[c0+0][r]=b0.x; Bs[c0+1][r]=b0.y; Bs[c0+2][r]=b0.z; Bs[c0+3][r]=b0.w;
        Bs[c0+4][r]=b1.x; Bs[c0+5][r]=b1.y; Bs[c0+6][r]=b1.z; Bs[c0+7][r]=b1.w;
        __syncthreads();

        #pragma unroll
        for (int k = 0; k < BK; k++) {
            float4 av = *(const float4*)&As[k][ty * 4];
            ull b01 = *(const ull*)&Bs[k][tx * 4];
            ull b23 = *(const ull*)&Bs[k][tx * 4 + 2];
            ull ap;
            ap = fpk_dup(av.x); c2[0][0] = fma2(ap, b01, c2[0][0]); c2[0][1] = fma2(ap, b23, c2[0][1]);
            ap = fpk_dup(av.y); c2[1][0] = fma2(ap, b01, c2[1][0]); c2[1][1] = fma2(ap, b23, c2[1][1]);
            ap = fpk_dup(av.z); c2[2][0] = fma2(ap, b01, c2[2][0]); c2[2][1] = fma2(ap, b23, c2[2][1]);
            ap = fpk_dup(av.w); c2[3][0] = fma2(ap, b01, c2[3][0]); c2[3][1] = fma2(ap, b23, c2[3][1]);
        }
        __syncthreads();
    }

    float4 bb = *(const float4*)(bias + nloc0 + tx * 4);
    #pragma unroll
    for (int mi = 0; mi < 4; mi++) {
        float2 p01 = unpk(c2[mi][0]);
        float2 p23 = unpk(c2[mi][1]);
        float4 o;
        o.x = p01.x + bb.x; o.y = p01.y + bb.y;
        o.z = p23.x + bb.z; o.w = p23.y + bb.w;
        int m = bx * BM + ty * 4 + mi;
        *(float4*)(Cout + (size_t)m * DIM + nloc0 + tx * 4) = o;
    }
}

// ---------------------------------------------------------------------------
// Kernel 2: linear term  g_lin[b,d] = 128 * (sum_i Xl[b,i,d] + sum_j Xr[b,j,d])
// ---------------------------------------------------------------------------
__global__ void __launch_bounds__(256) k_colsum()
{
    const int b = blockIdx.x;
    const int d = threadIdx.x;
    const float* pl = g_XL + (size_t)b * SEQ * DIM + d;
    const float* pr = g_XR + (size_t)b * SEQ * DIM + d;
    float s = 0.f;
    #pragma unroll 8
    for (int i = 0; i < SEQ; i++) {
        s += pl[i * DIM] + pr[i * DIM];
    }
    g_lin[b * DIM + d] = 128.0f * s;
}

// ---------------------------------------------------------------------------
// Kernel 3: pairwise abs-sum partials
//   g_part[js,b,d] = sum_{i=0..127} sum_{j in split js} |Xl[b,i,d] + Xr[b,j,d]|
//   grid = (32 batches, 16 j-splits), 128 threads, each thread owns 2 d's (f32x2)
// ---------------------------------------------------------------------------
__global__ void __launch_bounds__(128) k_pair()
{
    const int b  = blockIdx.x;
    const int js = blockIdx.y;
    const int tid = threadIdx.x;

    __shared__ float xls[IT][DIM];

    const ull ABSM = 0x7FFFFFFF7FFFFFFFULL;

    // this thread's 8 xr values (packed pairs over d)
    ull xr[JT];
    {
        const float* base = g_XR + (size_t)(b * SEQ + js * JT) * DIM + tid * 2;
        #pragma unroll
        for (int j = 0; j < JT; j++)
            xr[j] = *(const ull*)(base + (size_t)j * DIM);
    }

    ull acc0 = 0, acc1 = 0, acc2 = 0, acc3 = 0;

    for (int i0 = 0; i0 < SEQ; i0 += IT) {
        // stage IT rows of Xl through shared memory (coalesced)
        #pragma unroll
        for (int rr = 0; rr < IT; rr++) {
            *(ull*)&xls[rr][tid * 2] =
                *(const ull*)(g_XL + (size_t)(b * SEQ + i0 + rr) * DIM + tid * 2);
        }
        __syncthreads();

        #pragma unroll
        for (int ii = 0; ii < IT; ii++) {
            ull xl = *(const ull*)&xls[ii][tid * 2];
            ull t;
            t = add2(xl, xr[0]); t &= ABSM; acc0 = add2(acc0, t);
            t = add2(xl, xr[1]); t &= ABSM; acc1 = add2(acc1, t);
            t = add2(xl, xr[2]); t &= ABSM; acc2 = add2(acc2, t);
            t = add2(xl, xr[3]); t &= ABSM; acc3 = add2(acc3, t);
            t = add2(xl, xr[4]); t &= ABSM; acc0 = add2(acc0, t);
            t = add2(xl, xr[5]); t &= ABSM; acc1 = add2(acc1, t);
            t = add2(xl, xr[6]); t &= ABSM; acc2 = add2(acc2, t);
            t = add2(xl, xr[7]); t &= ABSM; acc3 = add2(acc3, t);
        }
        __syncthreads();
    }

    acc0 = add2(acc0, acc1);
    acc2 = add2(acc2, acc3);
    acc0 = add2(acc0, acc2);
    float2 res = unpk(acc0);
    float* outp = g_part + (size_t)(js * BATCH + b) * DIM + tid * 2;
    outp[0] = res.x;
    outp[1] = res.y;
}

// ---------------------------------------------------------------------------
// Kernel 4: reduce partials -> pooled; out = pooled @ W_rn^T + n^2 * b_rn
// ---------------------------------------------------------------------------
__global__ void __launch_bounds__(256)
k_final(const float* __restrict__ Wrn, const float* __restrict__ brn,
        float* __restrict__ out)
{
    const int b = blockIdx.x;
    const int tid = threadIdx.x;   // = output n, and = d during reduce
    __shared__ float pooled[DIM];

    float p = g_lin[b * DIM + tid];
    #pragma unroll
    for (int s = 0; s < NSPLIT; s++)
        p += g_part[(size_t)(s * BATCH + b) * DIM + tid];
    pooled[tid] = 0.5f * p;
    __syncthreads();

    const float4* w = (const float4*)(Wrn + (size_t)tid * DIM);
    float acc = 0.f;
    #pragma unroll 8
    for (int d4 = 0; d4 < DIM / 4; d4++) {
        float4 wv = w[d4];
        acc += pooled[4*d4+0] * wv.x + pooled[4*d4+1] * wv.y
             + pooled[4*d4+2] * wv.z + pooled[4*d4+3] * wv.w;
    }
    out[b * DIM + tid] = acc + 16384.0f * brn[tid];
}

// ---------------------------------------------------------------------------
extern "C" void kernel_launch(void* const* d_in, const int* in_sizes, int n_in,
                              void* d_out, int out_size)
{
    const int*   X    = (const int*)  d_in[0];
    const float* emb  = (const float*)d_in[1];
    const float* Wl   = (const float*)d_in[2];
    const float* bl   = (const float*)d_in[3];
    const float* Wr   = (const float*)d_in[4];
    const float* br   = (const float*)d_in[5];
    const float* Wrn  = (const float*)d_in[6];
    const float* brn  = (const float*)d_in[7];
    float*       out  = (float*)d_out;

    k_gemm  <<<dim3(MROWS / BM, 8), 256>>>(X, emb, Wl, bl, Wr, br);
    k_colsum<<<BATCH, DIM>>>();
    k_pair  <<<dim3(BATCH, NSPLIT), 128>>>();
    k_final <<<BATCH, DIM>>>(Wrn, brn, out);
}

// round 8
// speedup vs baseline: 1.3798x; 1.3798x over previous
#include <cuda_runtime.h>
#include <cstdint>

// Problem constants
#define BATCH 32
#define SEQ   128
#define DIM   256
#define MROWS (BATCH*SEQ)     // 4096
#define NSPLIT 16
#define JT    (SEQ/NSPLIT)    // 8
#define IT    16

typedef unsigned long long ull;

// ---------------- scratch (device globals; no allocation allowed) -----------
__device__ float g_XL[MROWS * DIM];
__device__ float g_XR[MROWS * DIM];
__device__ float g_part[NSPLIT * BATCH * DIM];   // abs-sum + folded linear term

// ---------------- packed f32x2 helpers (sm_100+) ----------------------------
__device__ __forceinline__ ull fpk_dup(float x) {
    unsigned u = __float_as_uint(x);
    ull r;
    asm("mov.b64 %0, {%1, %1};" : "=l"(r) : "r"(u));
    return r;
}
__device__ __forceinline__ ull add2(ull a, ull b) {
    ull d;
    asm("add.rn.f32x2 %0, %1, %2;" : "=l"(d) : "l"(a), "l"(b));
    return d;
}
__device__ __forceinline__ ull fma2(ull a, ull b, ull c) {
    ull d;
    asm("fma.rn.f32x2 %0, %1, %2, %3;" : "=l"(d) : "l"(a), "l"(b), "l"(c));
    return d;
}
__device__ __forceinline__ float2 unpk(ull v) {
    unsigned lo, hi;
    asm("mov.b64 {%0, %1}, %2;" : "=r"(lo), "=r"(hi) : "l"(v));
    return make_float2(__uint_as_float(lo), __uint_as_float(hi));
}

// ---------------------------------------------------------------------------
// Kernel 1: fused embedding gather + dual GEMM, 128x128 tile, 8x8 per thread
//   grid = (4096/128 = 32, 4); by 0-1 -> W_l cols, by 2-3 -> W_r cols
// ---------------------------------------------------------------------------
#define BM 128
#define BN 128
#define BK 32
#define NTILES (DIM / BK)    // 8

__global__ void __launch_bounds__(256, 1)
k_gemm(const int* __restrict__ X, const float* __restrict__ emb,
       const float* __restrict__ Wl, const float* __restrict__ bl,
       const float* __restrict__ Wr, const float* __restrict__ br)
{
    __shared__ float As[BK][BM + 4];   // stride 132 floats = 528B (16B mult)
    __shared__ float Bs[BK][BN + 4];
    __shared__ int   toks[BM];

    const int tid = threadIdx.x;
    const int bx = blockIdx.x, by = blockIdx.y;
    const bool isr = (by >= 2);
    const float* W    = isr ? Wr : Wl;
    const float* bias = isr ? br : bl;
    float*       Cout = isr ? g_XR : g_XL;
    const int nloc0 = (by & 1) * BN;

    if (tid < BM) toks[tid] = X[bx * BM + tid];
    __syncthreads();

    // loader mapping: each thread owns one row (m = tid>>1) and half its k-cols
    const int m  = tid >> 1;
    const int c0 = (tid & 1) * 16;
    const float* arow = emb + (size_t)toks[m] * DIM + c0;
    const float* brow = W   + (size_t)(nloc0 + m) * DIM + c0;

    // compute mapping: ty owns 8 m-rows, tx owns 8 n-cols
    const int ty = tid >> 4;   // 0..15
    const int tx = tid & 15;   // 0..15

    ull c2[8][4];
    #pragma unroll
    for (int i = 0; i < 8; i++)
        #pragma unroll
        for (int j = 0; j < 4; j++) c2[i][j] = 0ull;

    float4 a4[4], b4[4];
    #pragma unroll
    for (int i = 0; i < 4; i++) {
        a4[i] = *(const float4*)(arow + i * 4);
        b4[i] = *(const float4*)(brow + i * 4);
    }

    for (int t = 0; t < NTILES; t++) {
        __syncthreads();   // previous tile's compute done before overwrite
        #pragma unroll
        for (int i = 0; i < 4; i++) {
            As[c0 + 4*i + 0][m] = a4[i].x; As[c0 + 4*i + 1][m] = a4[i].y;
            As[c0 + 4*i + 2][m] = a4[i].z; As[c0 + 4*i + 3][m] = a4[i].w;
            Bs[c0 + 4*i + 0][m] = b4[i].x; Bs[c0 + 4*i + 1][m] = b4[i].y;
            Bs[c0 + 4*i + 2][m] = b4[i].z; Bs[c0 + 4*i + 3][m] = b4[i].w;
        }
        __syncthreads();

        if (t + 1 < NTILES) {   // register prefetch of next tile, overlaps compute
            const float* an = arow + (t + 1) * BK;
            const float* bn = brow + (t + 1) * BK;
            #pragma unroll
            for (int i = 0; i < 4; i++) {
                a4[i] = *(const float4*)(an + i * 4);
                b4[i] = *(const float4*)(bn + i * 4);
            }
        }

        #pragma unroll 8
        for (int k = 0; k < BK; k++) {
            float4 af0 = *(const float4*)&As[k][ty * 8];
            float4 af1 = *(const float4*)&As[k][ty * 8 + 4];
            ull b0 = *(const ull*)&Bs[k][tx * 8 + 0];
            ull b1 = *(const ull*)&Bs[k][tx * 8 + 2];
            ull b2 = *(const ull*)&Bs[k][tx * 8 + 4];
            ull b3 = *(const ull*)&Bs[k][tx * 8 + 6];
            ull ad;
            ad = fpk_dup(af0.x);
            c2[0][0]=fma2(ad,b0,c2[0][0]); c2[0][1]=fma2(ad,b1,c2[0][1]);
            c2[0][2]=fma2(ad,b2,c2[0][2]); c2[0][3]=fma2(ad,b3,c2[0][3]);
            ad = fpk_dup(af0.y);
            c2[1][0]=fma2(ad,b0,c2[1][0]); c2[1][1]=fma2(ad,b1,c2[1][1]);
            c2[1][2]=fma2(ad,b2,c2[1][2]); c2[1][3]=fma2(ad,b3,c2[1][3]);
            ad = fpk_dup(af0.z);
            c2[2][0]=fma2(ad,b0,c2[2][0]); c2[2][1]=fma2(ad,b1,c2[2][1]);
            c2[2][2]=fma2(ad,b2,c2[2][2]); c2[2][3]=fma2(ad,b3,c2[2][3]);
            ad = fpk_dup(af0.w);
            c2[3][0]=fma2(ad,b0,c2[3][0]); c2[3][1]=fma2(ad,b1,c2[3][1]);
            c2[3][2]=fma2(ad,b2,c2[3][2]); c2[3][3]=fma2(ad,b3,c2[3][3]);
            ad = fpk_dup(af1.x);
            c2[4][0]=fma2(ad,b0,c2[4][0]); c2[4][1]=fma2(ad,b1,c2[4][1]);
            c2[4][2]=fma2(ad,b2,c2[4][2]); c2[4][3]=fma2(ad,b3,c2[4][3]);
            ad = fpk_dup(af1.y);
            c2[5][0]=fma2(ad,b0,c2[5][0]); c2[5][1]=fma2(ad,b1,c2[5][1]);
            c2[5][2]=fma2(ad,b2,c2[5][2]); c2[5][3]=fma2(ad,b3,c2[5][3]);
            ad = fpk_dup(af1.z);
            c2[6][0]=fma2(ad,b0,c2[6][0]); c2[6][1]=fma2(ad,b1,c2[6][1]);
            c2[6][2]=fma2(ad,b2,c2[6][2]); c2[6][3]=fma2(ad,b3,c2[6][3]);
            ad = fpk_dup(af1.w);
            c2[7][0]=fma2(ad,b0,c2[7][0]); c2[7][1]=fma2(ad,b1,c2[7][1]);
            c2[7][2]=fma2(ad,b2,c2[7][2]); c2[7][3]=fma2(ad,b3,c2[7][3]);
        }
    }

    // epilogue: bias add + store 8x8
    float4 bb0 = *(const float4*)(bias + nloc0 + tx * 8);
    float4 bb1 = *(const float4*)(bias + nloc0 + tx * 8 + 4);
    #pragma unroll
    for (int mi = 0; mi < 8; mi++) {
        float2 p0 = unpk(c2[mi][0]);
        float2 p1 = unpk(c2[mi][1]);
        float2 p2 = unpk(c2[mi][2]);
        float2 p3 = unpk(c2[mi][3]);
        float4 o0, o1;
        o0.x = p0.x + bb0.x; o0.y = p0.y + bb0.y;
        o0.z = p1.x + bb0.z; o0.w = p1.y + bb0.w;
        o1.x = p2.x + bb1.x; o1.y = p2.y + bb1.y;
        o1.z = p3.x + bb1.z; o1.w = p3.y + bb1.w;
        const int mm = bx * BM + ty * 8 + mi;
        *(float4*)(Cout + (size_t)mm * DIM + nloc0 + tx * 8)     = o0;
        *(float4*)(Cout + (size_t)mm * DIM + nloc0 + tx * 8 + 4) = o1;
    }
}

// ---------------------------------------------------------------------------
// Kernel 2: pairwise abs-sum partials WITH folded linear term
//   part[js,b,d] = sum_{i,j in js} |xl_i+xr_j|  +  8*sum_i xl_i  +  128*sum_{j in js} xr_j
//   (so that sum over js = abs_total + 128*Sxl + 128*Sxr)
// ---------------------------------------------------------------------------
__global__ void __launch_bounds__(128) k_pair()
{
    const int b  = blockIdx.x;
    const int js = blockIdx.y;
    const int tid = threadIdx.x;

    __shared__ float xls[IT][DIM];

    const ull ABSM = 0x7FFFFFFF7FFFFFFFULL;

    ull xr[JT];
    {
        const float* base = g_XR + (size_t)(b * SEQ + js * JT) * DIM + tid * 2;
        #pragma unroll
        for (int j = 0; j < JT; j++)
            xr[j] = *(const ull*)(base + (size_t)j * DIM);
    }
    ull xrsum = xr[0];
    #pragma unroll
    for (int j = 1; j < JT; j++) xrsum = add2(xrsum, xr[j]);

    ull acc0 = 0, acc1 = 0, acc2 = 0, acc3 = 0;
    ull xlacc = 0;

    for (int i0 = 0; i0 < SEQ; i0 += IT) {
        #pragma unroll
        for (int rr = 0; rr < IT; rr++) {
            *(ull*)&xls[rr][tid * 2] =
                *(const ull*)(g_XL + (size_t)(b * SEQ + i0 + rr) * DIM + tid * 2);
        }
        __syncthreads();

        #pragma unroll
        for (int ii = 0; ii < IT; ii++) {
            ull xl = *(const ull*)&xls[ii][tid * 2];
            xlacc = add2(xlacc, xl);
            ull t;
            t = add2(xl, xr[0]); t &= ABSM; acc0 = add2(acc0, t);
            t = add2(xl, xr[1]); t &= ABSM; acc1 = add2(acc1, t);
            t = add2(xl, xr[2]); t &= ABSM; acc2 = add2(acc2, t);
            t = add2(xl, xr[3]); t &= ABSM; acc3 = add2(acc3, t);
            t = add2(xl, xr[4]); t &= ABSM; acc0 = add2(acc0, t);
            t = add2(xl, xr[5]); t &= ABSM; acc1 = add2(acc1, t);
            t = add2(xl, xr[6]); t &= ABSM; acc2 = add2(acc2, t);
            t = add2(xl, xr[7]); t &= ABSM; acc3 = add2(acc3, t);
        }
        __syncthreads();
    }

    acc0 = add2(acc0, acc1);
    acc2 = add2(acc2, acc3);
    acc0 = add2(acc0, acc2);
    // fold linear term: + 8*xlacc + 128*xrsum
    acc0 = fma2(fpk_dup(8.0f),   xlacc, acc0);
    acc0 = fma2(fpk_dup(128.0f), xrsum, acc0);

    float2 res = unpk(acc0);
    float* outp = g_part + (size_t)(js * BATCH + b) * DIM + tid * 2;
    outp[0] = res.x;
    outp[1] = res.y;
}

// ---------------------------------------------------------------------------
// Kernel 3: reduce partials -> pooled; out = pooled @ W_rn^T + n^2 * b_rn
//   grid = (32 batches, 8 n-chunks of 32); 8 threads cooperate per output n
// ---------------------------------------------------------------------------
__global__ void __launch_bounds__(256)
k_final(const float* __restrict__ Wrn, const float* __restrict__ brn,
        float* __restrict__ out)
{
    const int b   = blockIdx.x;
    const int nc  = blockIdx.y;
    const int tid = threadIdx.x;
    __shared__ float pooled[DIM];

    // phase 1: pooled[d] = 0.5 * sum_s part[s][b][d]  (16 independent L2 loads)
    {
        float p = 0.f;
        #pragma unroll
        for (int s = 0; s < NSPLIT; s++)
            p += g_part[(size_t)(s * BATCH + b) * DIM + tid];
        pooled[tid] = 0.5f * p;
    }
    __syncthreads();

    // phase 2: 8 lanes per output n, each covers 32 d's
    const int n  = nc * 32 + (tid >> 3);
    const int d0 = (tid & 7) * 32;
    const float4* w  = (const float4*)(Wrn + (size_t)n * DIM + d0);
    const float4* pp = (const float4*)(pooled + d0);
    float acc = 0.f;
    #pragma unroll
    for (int i = 0; i < 8; i++) {
        float4 wv = w[i];
        float4 pv = pp[i];
        acc += wv.x * pv.x + wv.y * pv.y + wv.z * pv.z + wv.w * pv.w;
    }
    acc += __shfl_down_sync(0xffffffffu, acc, 4, 8);
    acc += __shfl_down_sync(0xffffffffu, acc, 2, 8);
    acc += __shfl_down_sync(0xffffffffu, acc, 1, 8);
    if ((tid & 7) == 0)
        out[b * DIM + n] = acc + 16384.0f * brn[n];
}

// ---------------------------------------------------------------------------
extern "C" void kernel_launch(void* const* d_in, const int* in_sizes, int n_in,
                              void* d_out, int out_size)
{
    const int*   X    = (const int*)  d_in[0];
    const float* emb  = (const float*)d_in[1];
    const float* Wl   = (const float*)d_in[2];
    const float* bl   = (const float*)d_in[3];
    const float* Wr   = (const float*)d_in[4];
    const float* br   = (const float*)d_in[5];
    const float* Wrn  = (const float*)d_in[6];
    const float* brn  = (const float*)d_in[7];
    float*       out  = (float*)d_out;

    k_gemm <<<dim3(MROWS / BM, 4), 256>>>(X, emb, Wl, bl, Wr, br);
    k_pair <<<dim3(BATCH, NSPLIT), 128>>>();
    k_final<<<dim3(BATCH, 8), 256>>>(Wrn, brn, out);
}

// round 13
// speedup vs baseline: 1.4743x; 1.0685x over previous
#include <cuda_runtime.h>
#include <cstdint>

// Problem constants
#define BATCH 32
#define SEQ   128
#define DIM   256
#define MROWS (BATCH*SEQ)     // 4096
#define NSPLIT 16
#define JT    (SEQ/NSPLIT)    // 8
#define IT    16

typedef unsigned long long ull;

// ---------------- scratch (device globals; no allocation allowed) -----------
__device__ float g_XL[MROWS * DIM];
__device__ float g_XR[MROWS * DIM];
__device__ float g_part[NSPLIT * BATCH * DIM];   // abs-sum + folded linear term

// ---------------- packed f32x2 helpers (sm_100+) ----------------------------
__device__ __forceinline__ ull fpk_dup(float x) {
    unsigned u = __float_as_uint(x);
    ull r;
    asm("mov.b64 %0, {%1, %1};" : "=l"(r) : "r"(u));
    return r;
}
__device__ __forceinline__ ull fpk2(float x, float y) {
    ull r;
    asm("mov.b64 %0, {%1, %2};" : "=l"(r)
        : "r"(__float_as_uint(x)), "r"(__float_as_uint(y)));
    return r;
}
__device__ __forceinline__ ull add2(ull a, ull b) {
    ull d;
    asm("add.rn.f32x2 %0, %1, %2;" : "=l"(d) : "l"(a), "l"(b));
    return d;
}
__device__ __forceinline__ ull fma2(ull a, ull b, ull c) {
    ull d;
    asm("fma.rn.f32x2 %0, %1, %2, %3;" : "=l"(d) : "l"(a), "l"(b), "l"(c));
    return d;
}
__device__ __forceinline__ float2 unpk(ull v) {
    unsigned lo, hi;
    asm("mov.b64 {%0, %1}, %2;" : "=r"(lo), "=r"(hi) : "l"(v));
    return make_float2(__uint_as_float(lo), __uint_as_float(hi));
}

// ---------------- cp.async helpers ------------------------------------------
__device__ __forceinline__ void cpa16(uint32_t saddr, const void* gaddr) {
    asm volatile("cp.async.cg.shared.global [%0], [%1], 16;"
                 :: "r"(saddr), "l"(gaddr));
}
#define CP_COMMIT() asm volatile("cp.async.commit_group;")
#define CP_WAIT1()  asm volatile("cp.async.wait_group 1;")

// ---------------------------------------------------------------------------
// Kernel 1: fused embedding gather + dual GEMM
//   k-packed fma2, 128x128 tile, 512 threads, 8m x 4n per thread.
//   cp.async double-buffered STATIC smem (2 stages of BK=16, 40 KB total —
//   under the 48 KB no-attribute limit; no cudaFuncSetAttribute needed).
//   grid = (32, 4); by 0-1 -> W_l n-halves, by 2-3 -> W_r n-halves
// ---------------------------------------------------------------------------
#define BM 128
#define BN 128
#define BKK 16                       // k per stage
#define NSTAGES (DIM / BKK)          // 16
#define PITCH 20                     // floats/row: 80B (16B-aligned rows),
                                     // LDS.128 banks 20l%32 distinct -> conflict-free
#define A_FLOATS (BM * PITCH)        // 2560
#define STAGE_FLOATS (2 * A_FLOATS)  // A + B = 5120 floats = 20 KB

__global__ void __launch_bounds__(512)
k_gemm(const int* __restrict__ X, const float* __restrict__ emb,
       const float* __restrict__ Wl, const float* __restrict__ bl,
       const float* __restrict__ Wr, const float* __restrict__ br)
{
    __shared__ float sm[2 * STAGE_FLOATS];   // 40 KB static
    __shared__ int   toks[BM];

    const int tid = threadIdx.x;
    const int bx = blockIdx.x, by = blockIdx.y;
    const bool isr = (by >= 2);
    const float* W    = isr ? Wr : Wl;
    const float* bias = isr ? br : bl;
    float*       Cout = isr ? g_XR : g_XL;
    const int nloc0 = (by & 1) * BN;

    if (tid < BM) toks[tid] = X[bx * BM + tid];
    __syncthreads();

    const uint32_t sb = (uint32_t)__cvta_generic_to_shared(sm);

    // loader mapping: one 16B chunk of A + one of B per thread per stage
    const int lrow = tid >> 2;          // 0..127
    const int lc4  = (tid & 3) * 4;     // 0,4,8,12

    // compute mapping
    const int lane = tid & 31;          // n base: lane (+32*ni)
    const int m0   = (tid >> 5) * 8;    // 8 m-rows per thread (16 warps x 8 = 128)

    ull c2[8][4];
    #pragma unroll
    for (int i = 0; i < 8; i++)
        #pragma unroll
        for (int j = 0; j < 4; j++) c2[i][j] = 0ull;

    const float* arow_g = emb + (size_t)toks[lrow] * DIM + lc4;
    const float* brow_g = W   + (size_t)(nloc0 + lrow) * DIM + lc4;
    const uint32_t a_s  = sb + (uint32_t)(lrow * PITCH + lc4) * 4u;
    const uint32_t b_s  = a_s + A_FLOATS * 4u;

    // ---- stage loader (cp.async): 1 A-chunk + 1 B-chunk per thread ----
    auto load_stage = [&](int buf, int k0) {
        const uint32_t off = (uint32_t)(buf * STAGE_FLOATS) * 4u;
        cpa16(a_s + off, arow_g + k0);
        cpa16(b_s + off, brow_g + k0);
    };

    load_stage(0, 0);
    CP_COMMIT();
    load_stage(1, BKK);
    CP_COMMIT();

    #pragma unroll
    for (int t = 0; t < NSTAGES; t++) {
        CP_WAIT1();
        __syncthreads();

        const int buf = t & 1;
        const float* As = sm + buf * STAGE_FLOATS;
        const float* Bs = As + A_FLOATS;

        #pragma unroll
        for (int k4 = 0; k4 < BKK / 4; k4++) {
            ull b[4][2];
            #pragma unroll
            for (int ni = 0; ni < 4; ni++) {
                float4 bv = *(const float4*)&Bs[(lane + ni * 32) * PITCH + k4 * 4];
                b[ni][0] = fpk2(bv.x, bv.y);
                b[ni][1] = fpk2(bv.z, bv.w);
            }
            #pragma unroll
            for (int mi = 0; mi < 8; mi++) {
                // warp-uniform row -> LDS.64 broadcast, no pack movs
                ull alo = *(const ull*)&As[(m0 + mi) * PITCH + k4 * 4];
                ull ahi = *(const ull*)&As[(m0 + mi) * PITCH + k4 * 4 + 2];
                c2[mi][0] = fma2(alo, b[0][0], c2[mi][0]);
                c2[mi][1] = fma2(alo, b[1][0], c2[mi][1]);
                c2[mi][2] = fma2(alo, b[2][0], c2[mi][2]);
                c2[mi][3] = fma2(alo, b[3][0], c2[mi][3]);
                c2[mi][0] = fma2(ahi, b[0][1], c2[mi][0]);
                c2[mi][1] = fma2(ahi, b[1][1], c2[mi][1]);
                c2[mi][2] = fma2(ahi, b[2][1], c2[mi][2]);
                c2[mi][3] = fma2(ahi, b[3][1], c2[mi][3]);
            }
        }
        __syncthreads();

        if (t + 2 < NSTAGES)
            load_stage(buf, (t + 2) * BKK);
        CP_COMMIT();   // unconditional: uniform wait_group accounting
    }

    // epilogue: horizontal add of k-halves + bias, coalesced scalar stores
    float bb[4];
    #pragma unroll
    for (int ni = 0; ni < 4; ni++) bb[ni] = bias[nloc0 + lane + ni * 32];

    #pragma unroll
    for (int mi = 0; mi < 8; mi++) {
        float* orow = Cout + (size_t)(bx * BM + m0 + mi) * DIM + nloc0 + lane;
        #pragma unroll
        for (int ni = 0; ni < 4; ni++) {
            float2 h = unpk(c2[mi][ni]);
            orow[ni * 32] = h.x + h.y + bb[ni];
        }
    }
}

// ---------------------------------------------------------------------------
// Kernel 2: pairwise abs-sum partials WITH folded linear term
//   part[js,b,d] = sum_{i,j in js} |xl_i+xr_j| + 8*sum_i xl_i + 128*sum_{j in js} xr_j
// ---------------------------------------------------------------------------
__global__ void __launch_bounds__(128) k_pair()
{
    const int b  = blockIdx.x;
    const int js = blockIdx.y;
    const int tid = threadIdx.x;

    __shared__ float xls[IT][DIM];

    const ull ABSM = 0x7FFFFFFF7FFFFFFFULL;

    ull xr[JT];
    {
        const float* base = g_XR + (size_t)(b * SEQ + js * JT) * DIM + tid * 2;
        #pragma unroll
        for (int j = 0; j < JT; j++)
            xr[j] = *(const ull*)(base + (size_t)j * DIM);
    }
    ull xrsum = xr[0];
    #pragma unroll
    for (int j = 1; j < JT; j++) xrsum = add2(xrsum, xr[j]);

    ull acc0 = 0, acc1 = 0, acc2 = 0, acc3 = 0;
    ull xlacc = 0;

    for (int i0 = 0; i0 < SEQ; i0 += IT) {
        #pragma unroll
        for (int rr = 0; rr < IT; rr++) {
            *(ull*)&xls[rr][tid * 2] =
                *(const ull*)(g_XL + (size_t)(b * SEQ + i0 + rr) * DIM + tid * 2);
        }
        __syncthreads();

        #pragma unroll
        for (int ii = 0; ii < IT; ii++) {
            ull xl = *(const ull*)&xls[ii][tid * 2];
            xlacc = add2(xlacc, xl);
            ull t;
            t = add2(xl, xr[0]); t &= ABSM; acc0 = add2(acc0, t);
            t = add2(xl, xr[1]); t &= ABSM; acc1 = add2(acc1, t);
            t = add2(xl, xr[2]); t &= ABSM; acc2 = add2(acc2, t);
            t = add2(xl, xr[3]); t &= ABSM; acc3 = add2(acc3, t);
            t = add2(xl, xr[4]); t &= ABSM; acc0 = add2(acc0, t);
            t = add2(xl, xr[5]); t &= ABSM; acc1 = add2(acc1, t);
            t = add2(xl, xr[6]); t &= ABSM; acc2 = add2(acc2, t);
            t = add2(xl, xr[7]); t &= ABSM; acc3 = add2(acc3, t);
        }
        __syncthreads();
    }

    acc0 = add2(acc0, acc1);
    acc2 = add2(acc2, acc3);
    acc0 = add2(acc0, acc2);
    // fold linear term: + 8*xlacc + 128*xrsum
    acc0 = fma2(fpk_dup(8.0f),   xlacc, acc0);
    acc0 = fma2(fpk_dup(128.0f), xrsum, acc0);

    float2 res = unpk(acc0);
    float* outp = g_part + (size_t)(js * BATCH + b) * DIM + tid * 2;
    outp[0] = res.x;
    outp[1] = res.y;
}

// ---------------------------------------------------------------------------
// Kernel 3: reduce partials -> pooled; out = pooled @ W_rn^T + n^2 * b_rn
// ---------------------------------------------------------------------------
__global__ void __launch_bounds__(256)
k_final(const float* __restrict__ Wrn, const float* __restrict__ brn,
        float* __restrict__ out)
{
    const int b   = blockIdx.x;
    const int nc  = blockIdx.y;
    const int tid = threadIdx.x;
    __shared__ float pooled[DIM];

    {
        float p = 0.f;
        #pragma unroll
        for (int s = 0; s < NSPLIT; s++)
            p += g_part[(size_t)(s * BATCH + b) * DIM + tid];
        pooled[tid] = 0.5f * p;
    }
    __syncthreads();

    const int n  = nc * 32 + (tid >> 3);
    const int d0 = (tid & 7) * 32;
    const float4* w  = (const float4*)(Wrn + (size_t)n * DIM + d0);
    const float4* pp = (const float4*)(pooled + d0);
    float acc = 0.f;
    #pragma unroll
    for (int i = 0; i < 8; i++) {
        float4 wv = w[i];
        float4 pv = pp[i];
        acc += wv.x * pv.x + wv.y * pv.y + wv.z * pv.z + wv.w * pv.w;
    }
    acc += __shfl_down_sync(0xffffffffu, acc, 4, 8);
    acc += __shfl_down_sync(0xffffffffu, acc, 2, 8);
    acc += __shfl_down_sync(0xffffffffu, acc, 1, 8);
    if ((tid & 7) == 0)
        out[b * DIM + n] = acc + 16384.0f * brn[n];
}

// ---------------------------------------------------------------------------
extern "C" void kernel_launch(void* const* d_in, const int* in_sizes, int n_in,
                              void* d_out, int out_size)
{
    const int*   X    = (const int*)  d_in[0];
    const float* emb  = (const float*)d_in[1];
    const float* Wl   = (const float*)d_in[2];
    const float* bl   = (const float*)d_in[3];
    const float* Wr   = (const float*)d_in[4];
    const float* br   = (const float*)d_in[5];
    const float* Wrn  = (const float*)d_in[6];
    const float* brn  = (const float*)d_in[7];
    float*       out  = (float*)d_out;

    k_gemm <<<dim3(MROWS / BM, 4), 512>>>(X, emb, Wl, bl, Wr, br);
    k_pair <<<dim3(BATCH, NSPLIT), 128>>>();
    k_final<<<dim3(BATCH, 8), 256>>>(Wrn, brn, out);
}

// round 15
// speedup vs baseline: 1.4939x; 1.0133x over previous
#include <cuda_runtime.h>
#include <cstdint>

// Problem constants
#define BATCH 32
#define SEQ   128
#define DIM   256
#define MROWS (BATCH*SEQ)     // 4096
#define NSPLIT 16
#define JT    (SEQ/NSPLIT)    // 8
#define IT    16

typedef unsigned long long ull;

// ---------------- scratch (device globals; no allocation allowed) -----------
__device__ float g_XL[MROWS * DIM];
__device__ float g_XR[MROWS * DIM];
__device__ float g_part[NSPLIT * BATCH * DIM];   // abs-sum + folded linear term

// ---------------- packed f32x2 helpers (sm_100+) ----------------------------
__device__ __forceinline__ ull fpk_dup(float x) {
    unsigned u = __float_as_uint(x);
    ull r;
    asm("mov.b64 %0, {%1, %1};" : "=l"(r) : "r"(u));
    return r;
}
__device__ __forceinline__ ull add2(ull a, ull b) {
    ull d;
    asm("add.rn.f32x2 %0, %1, %2;" : "=l"(d) : "l"(a), "l"(b));
    return d;
}
__device__ __forceinline__ ull fma2(ull a, ull b, ull c) {
    ull d;
    asm("fma.rn.f32x2 %0, %1, %2, %3;" : "=l"(d) : "l"(a), "l"(b), "l"(c));
    return d;
}
__device__ __forceinline__ float2 unpk(ull v) {
    unsigned lo, hi;
    asm("mov.b64 {%0, %1}, %2;" : "=r"(lo), "=r"(hi) : "l"(v));
    return make_float2(__uint_as_float(lo), __uint_as_float(hi));
}

// ---------------- cp.async helpers ------------------------------------------
__device__ __forceinline__ void cpa16(uint32_t saddr, const void* gaddr) {
    asm volatile("cp.async.cg.shared.global [%0], [%1], 16;"
                 :: "r"(saddr), "l"(gaddr));
}
#define CP_COMMIT() asm volatile("cp.async.commit_group;")
#define CP_WAIT0()  asm volatile("cp.async.wait_group 0;")

// ---------------------------------------------------------------------------
// Kernel 1: fused embedding gather + dual GEMM
//   k-packed fma2, 128x128 tile, 512 threads, 8m x 4n per thread.
//   cp.async double-buffered STATIC smem (2 x BK=16 stages, 40 KB).
//   Single barrier per stage (prefetch-distance-1 pipeline).
//   All smem fragment loads are LDS.128 (ulonglong2) -> zero pack movs,
//   crossbar demand 1536 cyc/stage < fma 2048 cyc/stage.
//   grid = (32, 4); by 0-1 -> W_l n-halves, by 2-3 -> W_r n-halves
// ---------------------------------------------------------------------------
#define BM 128
#define BN 128
#define BKK 16                       // k per stage
#define NSTAGES (DIM / BKK)          // 16
#define PITCH 20                     // floats/row: 80B rows (16B-aligned);
                                     // LDS.128 phase banks 20l%32 all distinct
#define A_FLOATS (BM * PITCH)        // 2560
#define STAGE_FLOATS (2 * A_FLOATS)  // A + B = 5120 floats = 20 KB

__global__ void __launch_bounds__(512)
k_gemm(const int* __restrict__ X, const float* __restrict__ emb,
       const float* __restrict__ Wl, const float* __restrict__ bl,
       const float* __restrict__ Wr, const float* __restrict__ br)
{
    __shared__ float sm[2 * STAGE_FLOATS];   // 40 KB static
    __shared__ int   toks[BM];

    const int tid = threadIdx.x;
    const int bx = blockIdx.x, by = blockIdx.y;
    const bool isr = (by >= 2);
    const float* W    = isr ? Wr : Wl;
    const float* bias = isr ? br : bl;
    float*       Cout = isr ? g_XR : g_XL;
    const int nloc0 = (by & 1) * BN;

    if (tid < BM) toks[tid] = X[bx * BM + tid];
    __syncthreads();

    const uint32_t sb = (uint32_t)__cvta_generic_to_shared(sm);

    // loader mapping: one 16B chunk of A + one of B per thread per stage
    const int lrow = tid >> 2;          // 0..127
    const int lc4  = (tid & 3) * 4;     // 0,4,8,12

    // compute mapping
    const int lane = tid & 31;          // n base: lane (+32*ni)
    const int m0   = (tid >> 5) * 8;    // 8 m-rows per thread (16 warps x 8 = 128)

    ull c2[8][4];
    #pragma unroll
    for (int i = 0; i < 8; i++)
        #pragma unroll
        for (int j = 0; j < 4; j++) c2[i][j] = 0ull;

    const float* arow_g = emb + (size_t)toks[lrow] * DIM + lc4;
    const float* brow_g = W   + (size_t)(nloc0 + lrow) * DIM + lc4;
    const uint32_t a_s  = sb + (uint32_t)(lrow * PITCH + lc4) * 4u;
    const uint32_t b_s  = a_s + A_FLOATS * 4u;

    auto load_stage = [&](int buf, int k0) {
        const uint32_t off = (uint32_t)(buf * STAGE_FLOATS) * 4u;
        cpa16(a_s + off, arow_g + k0);
        cpa16(b_s + off, brow_g + k0);
    };

    load_stage(0, 0);
    CP_COMMIT();

    #pragma unroll
    for (int t = 0; t < NSTAGES; t++) {
        CP_WAIT0();
        __syncthreads();   // all warps done with stage t-1's buffer AND stage t data visible

        // issue next stage's load first -> overlaps this stage's compute
        if (t + 1 < NSTAGES) {
            load_stage((t + 1) & 1, (t + 1) * BKK);
            CP_COMMIT();
        }

        const int buf = t & 1;
        const float* As = sm + buf * STAGE_FLOATS;
        const float* Bs = As + A_FLOATS;

        #pragma unroll
        for (int k4 = 0; k4 < BKK / 4; k4++) {
            // B-fragments: 4 x LDS.128, pairs land register-aligned (no movs)
            ull b[4][2];
            #pragma unroll
            for (int ni = 0; ni < 4; ni++) {
                ulonglong2 bv = *(const ulonglong2*)&Bs[(lane + ni * 32) * PITCH + k4 * 4];
                b[ni][0] = bv.x;
                b[ni][1] = bv.y;
            }
            #pragma unroll
            for (int mi = 0; mi < 8; mi++) {
                // warp-uniform row -> single broadcast LDS.128
                ulonglong2 av = *(const ulonglong2*)&As[(m0 + mi) * PITCH + k4 * 4];
                c2[mi][0] = fma2(av.x, b[0][0], c2[mi][0]);
                c2[mi][1] = fma2(av.x, b[1][0], c2[mi][1]);
                c2[mi][2] = fma2(av.x, b[2][0], c2[mi][2]);
                c2[mi][3] = fma2(av.x, b[3][0], c2[mi][3]);
                c2[mi][0] = fma2(av.y, b[0][1], c2[mi][0]);
                c2[mi][1] = fma2(av.y, b[1][1], c2[mi][1]);
                c2[mi][2] = fma2(av.y, b[2][1], c2[mi][2]);
                c2[mi][3] = fma2(av.y, b[3][1], c2[mi][3]);
            }
        }
    }

    // epilogue: horizontal add of k-halves + bias, coalesced scalar stores
    float bb[4];
    #pragma unroll
    for (int ni = 0; ni < 4; ni++) bb[ni] = bias[nloc0 + lane + ni * 32];

    #pragma unroll
    for (int mi = 0; mi < 8; mi++) {
        float* orow = Cout + (size_t)(bx * BM + m0 + mi) * DIM + nloc0 + lane;
        #pragma unroll
        for (int ni = 0; ni < 4; ni++) {
            float2 h = unpk(c2[mi][ni]);
            orow[ni * 32] = h.x + h.y + bb[ni];
        }
    }
}

// ---------------------------------------------------------------------------
// Kernel 2: pairwise abs-sum partials WITH folded linear term
//   part[js,b,d] = sum_{i,j in js} |xl_i+xr_j| + 8*sum_i xl_i + 128*sum_{j in js} xr_j
// ---------------------------------------------------------------------------
__global__ void __launch_bounds__(128) k_pair()
{
    const int b  = blockIdx.x;
    const int js = blockIdx.y;
    const int tid = threadIdx.x;

    __shared__ float xls[IT][DIM];

    const ull ABSM = 0x7FFFFFFF7FFFFFFFULL;

    ull xr[JT];
    {
        const float* base = g_XR + (size_t)(b * SEQ + js * JT) * DIM + tid * 2;
        #pragma unroll
        for (int j = 0; j < JT; j++)
            xr[j] = *(const ull*)(base + (size_t)j * DIM);
    }
    ull xrsum = xr[0];
    #pragma unroll
    for (int j = 1; j < JT; j++) xrsum = add2(xrsum, xr[j]);

    ull acc0 = 0, acc1 = 0, acc2 = 0, acc3 = 0;
    ull xlacc = 0;

    for (int i0 = 0; i0 < SEQ; i0 += IT) {
        #pragma unroll
        for (int rr = 0; rr < IT; rr++) {
            *(ull*)&xls[rr][tid * 2] =
                *(const ull*)(g_XL + (size_t)(b * SEQ + i0 + rr) * DIM + tid * 2);
        }
        __syncthreads();

        #pragma unroll
        for (int ii = 0; ii < IT; ii++) {
            ull xl = *(const ull*)&xls[ii][tid * 2];
            xlacc = add2(xlacc, xl);
            ull t;
            t = add2(xl, xr[0]); t &= ABSM; acc0 = add2(acc0, t);
            t = add2(xl, xr[1]); t &= ABSM; acc1 = add2(acc1, t);
            t = add2(xl, xr[2]); t &= ABSM; acc2 = add2(acc2, t);
            t = add2(xl, xr[3]); t &= ABSM; acc3 = add2(acc3, t);
            t = add2(xl, xr[4]); t &= ABSM; acc0 = add2(acc0, t);
            t = add2(xl, xr[5]); t &= ABSM; acc1 = add2(acc1, t);
            t = add2(xl, xr[6]); t &= ABSM; acc2 = add2(acc2, t);
            t = add2(xl, xr[7]); t &= ABSM; acc3 = add2(acc3, t);
        }
        __syncthreads();
    }

    acc0 = add2(acc0, acc1);
    acc2 = add2(acc2, acc3);
    acc0 = add2(acc0, acc2);
    // fold linear term: + 8*xlacc + 128*xrsum
    acc0 = fma2(fpk_dup(8.0f),   xlacc, acc0);
    acc0 = fma2(fpk_dup(128.0f), xrsum, acc0);

    float2 res = unpk(acc0);
    float* outp = g_part + (size_t)(js * BATCH + b) * DIM + tid * 2;
    outp[0] = res.x;
    outp[1] = res.y;
}

// ---------------------------------------------------------------------------
// Kernel 3: reduce partials -> pooled; out = pooled @ W_rn^T + n^2 * b_rn
// ---------------------------------------------------------------------------
__global__ void __launch_bounds__(256)
k_final(const float* __restrict__ Wrn, const float* __restrict__ brn,
        float* __restrict__ out)
{
    const int b   = blockIdx.x;
    const int nc  = blockIdx.y;
    const int tid = threadIdx.x;
    __shared__ float pooled[DIM];

    {
        float p = 0.f;
        #pragma unroll
        for (int s = 0; s < NSPLIT; s++)
            p += g_part[(size_t)(s * BATCH + b) * DIM + tid];
        pooled[tid] = 0.5f * p;
    }
    __syncthreads();

    const int n  = nc * 32 + (tid >> 3);
    const int d0 = (tid & 7) * 32;
    const float4* w  = (const float4*)(Wrn + (size_t)n * DIM + d0);
    const float4* pp = (const float4*)(pooled + d0);
    float acc = 0.f;
    #pragma unroll
    for (int i = 0; i < 8; i++) {
        float4 wv = w[i];
        float4 pv = pp[i];
        acc += wv.x * pv.x + wv.y * pv.y + wv.z * pv.z + wv.w * pv.w;
    }
    acc += __shfl_down_sync(0xffffffffu, acc, 4, 8);
    acc += __shfl_down_sync(0xffffffffu, acc, 2, 8);
    acc += __shfl_down_sync(0xffffffffu, acc, 1, 8);
    if ((tid & 7) == 0)
        out[b * DIM + n] = acc + 16384.0f * brn[n];
}

// ---------------------------------------------------------------------------
extern "C" void kernel_launch(void* const* d_in, const int* in_sizes, int n_in,
                              void* d_out, int out_size)
{
    const int*   X    = (const int*)  d_in[0];
    const float* emb  = (const float*)d_in[1];
    const float* Wl   = (const float*)d_in[2];
    const float* bl   = (const float*)d_in[3];
    const float* Wr   = (const float*)d_in[4];
    const float* br   = (const float*)d_in[5];
    const float* Wrn  = (const float*)d_in[6];
    const float* brn  = (const float*)d_in[7];
    float*       out  = (float*)d_out;

    k_gemm <<<dim3(MROWS / BM, 4), 512>>>(X, emb, Wl, bl, Wr, br);
    k_pair <<<dim3(BATCH, NSPLIT), 128>>>();
    k_final<<<dim3(BATCH, 8), 256>>>(Wrn, brn, out);
}

// round 16
// speedup vs baseline: 1.9992x; 1.3382x over previous
#include <cuda_runtime.h>
#include <cstdint>

// Problem constants
#define BATCH 32
#define SEQ   128
#define DIM   256
#define MROWS (BATCH*SEQ)     // 4096
#define NSPLIT 16
#define JT    (SEQ/NSPLIT)    // 8
#define IT    16

typedef unsigned long long ull;

// ---------------- scratch (device globals; no allocation allowed) -----------
__device__ float g_XL[MROWS * DIM];
__device__ float g_XR[MROWS * DIM];
__device__ float g_part[NSPLIT * BATCH * DIM];   // abs-sum + folded linear term

// ---------------- packed f32x2 helpers (sm_100+) ----------------------------
__device__ __forceinline__ ull fpk_dup(float x) {
    unsigned u = __float_as_uint(x);
    ull r;
    asm("mov.b64 %0, {%1, %1};" : "=l"(r) : "r"(u));
    return r;
}
__device__ __forceinline__ ull add2(ull a, ull b) {
    ull d;
    asm("add.rn.f32x2 %0, %1, %2;" : "=l"(d) : "l"(a), "l"(b));
    return d;
}
__device__ __forceinline__ ull fma2(ull a, ull b, ull c) {
    ull d;
    asm("fma.rn.f32x2 %0, %1, %2, %3;" : "=l"(d) : "l"(a), "l"(b), "l"(c));
    return d;
}
__device__ __forceinline__ float2 unpk(ull v) {
    unsigned lo, hi;
    asm("mov.b64 {%0, %1}, %2;" : "=r"(lo), "=r"(hi) : "l"(v));
    return make_float2(__uint_as_float(lo), __uint_as_float(hi));
}

// ---------------- cp.async helpers ------------------------------------------
__device__ __forceinline__ void cpa16(uint32_t saddr, const void* gaddr) {
    asm volatile("cp.async.cg.shared.global [%0], [%1], 16;"
                 :: "r"(saddr), "l"(gaddr));
}
#define CP_COMMIT() asm volatile("cp.async.commit_group;")
#define CP_WAIT0()  asm volatile("cp.async.wait_group 0;")

// ---------------- tf32 mma helpers ------------------------------------------
__device__ __forceinline__ uint32_t to_tf32(uint32_t x) {
    uint32_t r;
    asm("cvt.rna.tf32.f32 %0, %1;" : "=r"(r) : "r"(x));
    return r;
}
__device__ __forceinline__ void ldm_x4(uint32_t& r0, uint32_t& r1,
                                       uint32_t& r2, uint32_t& r3, uint32_t addr) {
    asm volatile("ldmatrix.sync.aligned.m8n8.x4.shared.b16 {%0,%1,%2,%3}, [%4];"
                 : "=r"(r0), "=r"(r1), "=r"(r2), "=r"(r3) : "r"(addr));
}
__device__ __forceinline__ void mma_tf32(float* c, const uint32_t* a,
                                         uint32_t b0, uint32_t b1) {
    asm volatile("mma.sync.aligned.m16n8k8.row.col.f32.tf32.tf32.f32 "
                 "{%0,%1,%2,%3}, {%4,%5,%6,%7}, {%8,%9}, {%0,%1,%2,%3};"
                 : "+f"(c[0]), "+f"(c[1]), "+f"(c[2]), "+f"(c[3])
                 : "r"(a[0]), "r"(a[1]), "r"(a[2]), "r"(a[3]), "r"(b0), "r"(b1));
}

// ---------------------------------------------------------------------------
// Kernel 1: fused embedding gather + dual GEMM — tf32 tensor cores
//   128x128 tile, 256 threads (8 warps, warp tile 32m x 64n),
//   mma.sync.m16n8k8.tf32, fragments via ldmatrix.x4 on 4-byte tiles,
//   cp.async double-buffered static smem (2 x BK=16 stages, 40 KB).
//   grid = (32, 4); by 0-1 -> W_l n-halves, by 2-3 -> W_r n-halves
// ---------------------------------------------------------------------------
#define BM 128
#define BN 128
#define BKK 16                       // k per stage (2 k8 steps)
#define NSTAGES (DIM / BKK)          // 16
#define PITCH 20                     // floats/row: 80B rows; ldmatrix row addrs
                                     // hit all-distinct bank groups
#define A_FLOATS (BM * PITCH)        // 2560
#define STAGE_FLOATS (2 * A_FLOATS)  // A + B = 5120 floats = 20 KB

__global__ void __launch_bounds__(256)
k_gemm(const int* __restrict__ X, const float* __restrict__ emb,
       const float* __restrict__ Wl, const float* __restrict__ bl,
       const float* __restrict__ Wr, const float* __restrict__ br)
{
    __shared__ float sm[2 * STAGE_FLOATS];   // 40 KB static
    __shared__ int   toks[BM];

    const int tid = threadIdx.x;
    const int bx = blockIdx.x, by = blockIdx.y;
    const bool isr = (by >= 2);
    const float* W    = isr ? Wr : Wl;
    const float* bias = isr ? br : bl;
    float*       Cout = isr ? g_XR : g_XL;
    const int nloc0 = (by & 1) * BN;

    if (tid < BM) toks[tid] = X[bx * BM + tid];
    __syncthreads();

    const uint32_t sb = (uint32_t)__cvta_generic_to_shared(sm);

    // loader mapping: 2 A-chunks + 2 B-chunks (16B) per thread per stage
    const int lrow = tid >> 1;          // 0..127
    const int lc0  = (tid & 1) * 8;     // 0 or 8

    const float* arow_g = emb + (size_t)toks[lrow] * DIM + lc0;
    const float* brow_g = W   + (size_t)(nloc0 + lrow) * DIM + lc0;
    const uint32_t a_s  = sb + (uint32_t)(lrow * PITCH + lc0) * 4u;
    const uint32_t b_s  = a_s + A_FLOATS * 4u;

    auto load_stage = [&](int buf, int k0) {
        const uint32_t off = (uint32_t)(buf * STAGE_FLOATS) * 4u;
        cpa16(a_s + off,       arow_g + k0);
        cpa16(a_s + off + 16u, arow_g + k0 + 4);
        cpa16(b_s + off,       brow_g + k0);
        cpa16(b_s + off + 16u, brow_g + k0 + 4);
    };

    // compute mapping: 8 warps = 4(m) x 2(n); warp tile 32m x 64n
    const int warp = tid >> 5;
    const int lane = tid & 31;
    const int M0w  = (warp >> 1) * 32;
    const int N0w  = (warp & 1) * 64;

    // ldmatrix lane-role offsets
    const int aRowOff = (lane & 7) + ((lane >> 3) & 1) * 8;  // row within m16
    const int aColOff = (lane >> 4) * 4;                     // k-half
    const int bRowOff = (lane >> 4) * 8 + (lane & 7);        // row within n16
    const int bColOff = ((lane >> 3) & 1) * 4;               // k-half

    float c[2][8][4];
    #pragma unroll
    for (int mt = 0; mt < 2; mt++)
        #pragma unroll
        for (int na = 0; na < 8; na++)
            #pragma unroll
            for (int q = 0; q < 4; q++) c[mt][na][q] = 0.f;

    load_stage(0, 0);
    CP_COMMIT();

    for (int t = 0; t < NSTAGES; t++) {
        CP_WAIT0();
        __syncthreads();

        if (t + 1 < NSTAGES) {
            load_stage((t + 1) & 1, (t + 1) * BKK);
            CP_COMMIT();
        }

        const uint32_t stage = sb + (uint32_t)((t & 1) * STAGE_FLOATS) * 4u;
        const uint32_t bstage = stage + A_FLOATS * 4u;

        #pragma unroll
        for (int k8 = 0; k8 < 2; k8++) {
            const int K0 = k8 * 8;

            // A fragments: one ldmatrix.x4 per m16 atom
            uint32_t a[2][4];
            #pragma unroll
            for (int mt = 0; mt < 2; mt++) {
                uint32_t addr = stage +
                    (uint32_t)((M0w + mt * 16 + aRowOff) * PITCH + K0 + aColOff) * 4u;
                ldm_x4(a[mt][0], a[mt][1], a[mt][2], a[mt][3], addr);
                #pragma unroll
                for (int q = 0; q < 4; q++) a[mt][q] = to_tf32(a[mt][q]);
            }

            // B fragments: one ldmatrix.x4 per n16 pair (regs 0,1 -> n8 lo; 2,3 -> n8 hi)
            #pragma unroll
            for (int np = 0; np < 4; np++) {
                uint32_t b0, b1, b2, b3;
                uint32_t addr = bstage +
                    (uint32_t)((N0w + np * 16 + bRowOff) * PITCH + K0 + bColOff) * 4u;
                ldm_x4(b0, b1, b2, b3, addr);
                b0 = to_tf32(b0); b1 = to_tf32(b1);
                b2 = to_tf32(b2); b3 = to_tf32(b3);

                mma_tf32(c[0][np * 2 + 0], a[0], b0, b1);
                mma_tf32(c[0][np * 2 + 1], a[0], b2, b3);
                mma_tf32(c[1][np * 2 + 0], a[1], b0, b1);
                mma_tf32(c[1][np * 2 + 1], a[1], b2, b3);
            }
        }
    }

    // epilogue: bias + store. C frag: lane g=lane>>2, cq=lane&3:
    //   c0,c1 -> row g,   cols 2cq,2cq+1 ; c2,c3 -> row g+8
    {
        const int g  = lane >> 2;
        const int cq = lane & 3;
        #pragma unroll
        for (int mt = 0; mt < 2; mt++) {
            #pragma unroll
            for (int na = 0; na < 8; na++) {
                const int gc = nloc0 + N0w + na * 8 + 2 * cq;
                const float b0v = bias[gc], b1v = bias[gc + 1];
                const int r0 = bx * BM + M0w + mt * 16 + g;
                float2 lo = make_float2(c[mt][na][0] + b0v, c[mt][na][1] + b1v);
                float2 hi = make_float2(c[mt][na][2] + b0v, c[mt][na][3] + b1v);
                *(float2*)(Cout + (size_t)r0 * DIM + gc)       = lo;
                *(float2*)(Cout + (size_t)(r0 + 8) * DIM + gc) = hi;
            }
        }
    }
}

// ---------------------------------------------------------------------------
// Kernel 2: pairwise abs-sum partials WITH folded linear term
//   part[js,b,d] = sum_{i,j in js} |xl_i+xr_j| + 8*sum_i xl_i + 128*sum_{j in js} xr_j
// ---------------------------------------------------------------------------
__global__ void __launch_bounds__(128) k_pair()
{
    const int b  = blockIdx.x;
    const int js = blockIdx.y;
    const int tid = threadIdx.x;

    __shared__ float xls[IT][DIM];

    const ull ABSM = 0x7FFFFFFF7FFFFFFFULL;

    ull xr[JT];
    {
        const float* base = g_XR + (size_t)(b * SEQ + js * JT) * DIM + tid * 2;
        #pragma unroll
        for (int j = 0; j < JT; j++)
            xr[j] = *(const ull*)(base + (size_t)j * DIM);
    }
    ull xrsum = xr[0];
    #pragma unroll
    for (int j = 1; j < JT; j++) xrsum = add2(xrsum, xr[j]);

    ull acc0 = 0, acc1 = 0, acc2 = 0, acc3 = 0;
    ull xlacc = 0;

    for (int i0 = 0; i0 < SEQ; i0 += IT) {
        #pragma unroll
        for (int rr = 0; rr < IT; rr++) {
            *(ull*)&xls[rr][tid * 2] =
                *(const ull*)(g_XL + (size_t)(b * SEQ + i0 + rr) * DIM + tid * 2);
        }
        __syncthreads();

        #pragma unroll
        for (int ii = 0; ii < IT; ii++) {
            ull xl = *(const ull*)&xls[ii][tid * 2];
            xlacc = add2(xlacc, xl);
            ull t;
            t = add2(xl, xr[0]); t &= ABSM; acc0 = add2(acc0, t);
            t = add2(xl, xr[1]); t &= ABSM; acc1 = add2(acc1, t);
            t = add2(xl, xr[2]); t &= ABSM; acc2 = add2(acc2, t);
            t = add2(xl, xr[3]); t &= ABSM; acc3 = add2(acc3, t);
            t = add2(xl, xr[4]); t &= ABSM; acc0 = add2(acc0, t);
            t = add2(xl, xr[5]); t &= ABSM; acc1 = add2(acc1, t);
            t = add2(xl, xr[6]); t &= ABSM; acc2 = add2(acc2, t);
            t = add2(xl, xr[7]); t &= ABSM; acc3 = add2(acc3, t);
        }
        __syncthreads();
    }

    acc0 = add2(acc0, acc1);
    acc2 = add2(acc2, acc3);
    acc0 = add2(acc0, acc2);
    // fold linear term: + 8*xlacc + 128*xrsum
    acc0 = fma2(fpk_dup(8.0f),   xlacc, acc0);
    acc0 = fma2(fpk_dup(128.0f), xrsum, acc0);

    float2 res = unpk(acc0);
    float* outp = g_part + (size_t)(js * BATCH + b) * DIM + tid * 2;
    outp[0] = res.x;
    outp[1] = res.y;
}

// ---------------------------------------------------------------------------
// Kernel 3: reduce partials -> pooled; out = pooled @ W_rn^T + n^2 * b_rn
// ---------------------------------------------------------------------------
__global__ void __launch_bounds__(256)
k_final(const float* __restrict__ Wrn, const float* __restrict__ brn,
        float* __restrict__ out)
{
    const int b   = blockIdx.x;
    const int nc  = blockIdx.y;
    const int tid = threadIdx.x;
    __shared__ float pooled[DIM];

    {
        float p = 0.f;
        #pragma unroll
        for (int s = 0; s < NSPLIT; s++)
            p += g_part[(size_t)(s * BATCH + b) * DIM + tid];
        pooled[tid] = 0.5f * p;
    }
    __syncthreads();

    const int n  = nc * 32 + (tid >> 3);
    const int d0 = (tid & 7) * 32;
    const float4* w  = (const float4*)(Wrn + (size_t)n * DIM + d0);
    const float4* pp = (const float4*)(pooled + d0);
    float acc = 0.f;
    #pragma unroll
    for (int i = 0; i < 8; i++) {
        float4 wv = w[i];
        float4 pv = pp[i];
        acc += wv.x * pv.x + wv.y * pv.y + wv.z * pv.z + wv.w * pv.w;
    }
    acc += __shfl_down_sync(0xffffffffu, acc, 4, 8);
    acc += __shfl_down_sync(0xffffffffu, acc, 2, 8);
    acc += __shfl_down_sync(0xffffffffu, acc, 1, 8);
    if ((tid & 7) == 0)
        out[b * DIM + n] = acc + 16384.0f * brn[n];
}

// ---------------------------------------------------------------------------
extern "C" void kernel_launch(void* const* d_in, const int* in_sizes, int n_in,
                              void* d_out, int out_size)
{
    const int*   X    = (const int*)  d_in[0];
    const float* emb  = (const float*)d_in[1];
    const float* Wl   = (const float*)d_in[2];
    const float* bl   = (const float*)d_in[3];
    const float* Wr   = (const float*)d_in[4];
    const float* br   = (const float*)d_in[5];
    const float* Wrn  = (const float*)d_in[6];
    const float* brn  = (const float*)d_in[7];
    float*       out  = (float*)d_out;

    k_gemm <<<dim3(MROWS / BM, 4), 256>>>(X, emb, Wl, bl, Wr, br);
    k_pair <<<dim3(BATCH, NSPLIT), 128>>>();
    k_final<<<dim3(BATCH, 8), 256>>>(Wrn, brn, out);
}